// round 6
// baseline (speedup 1.0000x reference)
#include <cuda_runtime.h>

// SepKANLayer1D: per-token KAN edge-spline layer.
// x: (4, 8, 65536) f32, w: (4, 640, 65536) f32, out: (4, 8, 65536) f32.
// Pure HBM stream: w read exactly once -> __ldcs. 8 threads per token
// (one output channel each, via blockIdx.y). Uniform-knot closed-form
// cubic B-spline (only 4 nonzero bases) replaces Cox-de-Boor recursion.

#define IN_C   8
#define OUT_C  8
#define NB     8
#define NTOK   65536
#define WSIZE  640

__global__ __launch_bounds__(128, 16)
void sepkan_kernel(const float* __restrict__ x,
                   const float* __restrict__ w,
                   float* __restrict__ out) {
    const int t = blockIdx.x * blockDim.x + threadIdx.x;   // 0 .. 262143 (token id)
    const int o = blockIdx.y;                              // output channel 0..7
    const int b = t >> 16;
    const int n = t & (NTOK - 1);

    const float* xp = x + (size_t)b * IN_C * NTOK + n;
    const float* wp = w + (size_t)b * WSIZE * NTOK + n;

    float acc = 0.0f;

#pragma unroll 1   // bounded code size; ~11 independent loads per iteration
    for (int i = 0; i < IN_C; ++i) {
        const float xi = __ldg(xp + i * NTOK);

        // ---- closed-form uniform cubic B-spline, grid [0,1], 5 intervals ----
        // interval m = floor(5x) (clamped), local u = 5x - m in [0,1).
        // nonzero bases m..m+3 with weights:
        //   b[m]   = (1-u)^3 / 6
        //   b[m+1] = (3u^3 - 6u^2 + 4) / 6
        //   b[m+2] = (-3u^3 + 3u^2 + 3u + 1) / 6
        //   b[m+3] = u^3 / 6
        int m = (int)(5.0f * xi);
        m = (m < 0) ? 0 : (m > 4 ? 4 : m);
        const float u  = 5.0f * xi - (float)m;
        const float v  = 1.0f - u;
        const float u2 = u * u, u3 = u2 * u;
        const float w0 = v * v * v * (1.0f / 6.0f);
        const float w1 = (3.0f * u3 - 6.0f * u2 + 4.0f) * (1.0f / 6.0f);
        const float w2 = (-3.0f * u3 + 3.0f * u2 + 3.0f * u + 1.0f) * (1.0f / 6.0f);
        const float w3 = u3 * (1.0f / 6.0f);

        const bool p0 = (m == 0), p1 = (m == 1), p2 = (m == 2), p3 = (m == 3);

        const float sx = xi / (1.0f + __expf(-xi));   // silu

        const float* wc = wp + (size_t)(i * OUT_C * NB + o * NB) * NTOK;
        const float* wu = wp + (size_t)(IN_C * OUT_C * NB + i * OUT_C + o) * NTOK;
        const float* wr = wp + (size_t)(IN_C * OUT_C * NB + IN_C * OUT_C + i * OUT_C + o) * NTOK;

        // load all 8 coefs (coalesced, streaming); dot only the 4 live ones.
        float c[NB];
#pragma unroll
        for (int k = 0; k < NB; ++k)
            c[k] = __ldcs(wc + (size_t)k * NTOK);

        const float c0 = p0 ? c[0] : p1 ? c[1] : p2 ? c[2] : p3 ? c[3] : c[4];
        const float c1 = p0 ? c[1] : p1 ? c[2] : p2 ? c[3] : p3 ? c[4] : c[5];
        const float c2 = p0 ? c[2] : p1 ? c[3] : p2 ? c[4] : p3 ? c[5] : c[6];
        const float c3 = p0 ? c[3] : p1 ? c[4] : p2 ? c[5] : p3 ? c[6] : c[7];

        float sp;
        sp = w0 * c0;
        sp = fmaf(w1, c1, sp);
        sp = fmaf(w2, c2, sp);
        sp = fmaf(w3, c3, sp);

        acc = fmaf(__ldcs(wu), sp, acc);
        acc = fmaf(sx, __ldcs(wr), acc);
    }

    out[((size_t)b * OUT_C + o) * NTOK + n] = acc;
}

extern "C" void kernel_launch(void* const* d_in, const int* in_sizes, int n_in,
                              void* d_out, int out_size) {
    const float* x = (const float*)d_in[0];   // (4, 8, 65536)
    const float* w = (const float*)d_in[1];   // (4, 640, 65536)
    float* out = (float*)d_out;               // (4, 8, 65536)

    const int total = 4 * NTOK;               // 262144 tokens
    dim3 grid(total / 128, OUT_C);            // (2048, 8)
    sepkan_kernel<<<grid, 128>>>(x, w, out);
}

// round 7
// speedup vs baseline: 1.2210x; 1.2210x over previous
#include <cuda_runtime.h>

// SepKANLayer1D: per-token KAN edge-spline layer.
// x: (4, 8, 65536) f32, w: (4, 640, 65536) f32, out: (4, 8, 65536) f32.
// Pure HBM stream: w read once -> __ldcs. 4 threads/token (OH=2 via blockIdx.y)
// = best warps x MLP/warp product (R5). Closed-form uniform-knot cubic basis
// scattered into w8[0..7] (one-time selects), inner dot = plain 8-FMA.

#define IN_C   8
#define OUT_C  8
#define NB     8
#define OH     2                // outputs per thread
#define NTOK   65536
#define WSIZE  640

__global__ __launch_bounds__(128, 16)
void sepkan_kernel(const float* __restrict__ x,
                   const float* __restrict__ w,
                   float* __restrict__ out) {
    const int t = blockIdx.x * blockDim.x + threadIdx.x;   // 0 .. 262143 (token id)
    const int ob = blockIdx.y * OH;                        // 0,2,4,6
    const int b = t >> 16;
    const int n = t & (NTOK - 1);

    const float* xp = x + (size_t)b * IN_C * NTOK + n;
    const float* wp = w + (size_t)b * WSIZE * NTOK + n;

    float acc0 = 0.0f, acc1 = 0.0f;

    float xi_next = __ldg(xp);                 // prefetch channel 0

#pragma unroll 1   // ~20 independent w-loads per iteration stay in flight
    for (int i = 0; i < IN_C; ++i) {
        const float xi = xi_next;
        if (i + 1 < IN_C) xi_next = __ldg(xp + (i + 1) * NTOK);

        // ---- closed-form uniform cubic B-spline, grid [0,1], 5 intervals ----
        // m = clamp(floor(5x),0,4), u = 5x-m. Nonzero bases m..m+3:
        //   (1-u)^3/6, (3u^3-6u^2+4)/6, (-3u^3+3u^2+3u+1)/6, u^3/6
        int m = (int)(5.0f * xi);
        m = (m < 0) ? 0 : (m > 4 ? 4 : m);
        const float u  = 5.0f * xi - (float)m;
        const float v  = 1.0f - u;
        const float u2 = u * u, u3 = u2 * u;
        const float w0 = v * v * v * (1.0f / 6.0f);
        const float w1 = (3.0f * u3 - 6.0f * u2 + 4.0f) * (1.0f / 6.0f);
        const float w2 = (-3.0f * u3 + 3.0f * u2 + 3.0f * u + 1.0f) * (1.0f / 6.0f);
        const float w3 = u3 * (1.0f / 6.0f);

        // scatter the 4 live weights into the 8-slot basis vector (once per i,
        // shared by both outputs); dead slots are exactly 0.
        float w8[NB];
#pragma unroll
        for (int k = 0; k < NB; ++k) {
            const int d = k - m;
            w8[k] = (d == 0) ? w0 : (d == 1) ? w1 : (d == 2) ? w2 : (d == 3) ? w3 : 0.0f;
        }

        const float sx = xi / (1.0f + __expf(-xi));   // silu

        const float* wc = wp + (size_t)(i * OUT_C * NB + ob * NB) * NTOK;
        const float* wu = wp + (size_t)(IN_C * OUT_C * NB + i * OUT_C + ob) * NTOK;
        const float* wr = wp + (size_t)(IN_C * OUT_C * NB + IN_C * OUT_C + i * OUT_C + ob) * NTOK;

        float sp0 = 0.0f, sp1 = 0.0f;
#pragma unroll
        for (int k = 0; k < NB; ++k) {
            sp0 = fmaf(w8[k], __ldcs(wc + (size_t)k * NTOK), sp0);
            sp1 = fmaf(w8[k], __ldcs(wc + (size_t)(NB + k) * NTOK), sp1);
        }
        acc0 = fmaf(__ldcs(wu),            sp0, acc0);
        acc1 = fmaf(__ldcs(wu + NTOK),     sp1, acc1);
        acc0 = fmaf(sx, __ldcs(wr),        acc0);
        acc1 = fmaf(sx, __ldcs(wr + NTOK), acc1);
    }

    float* yp = out + ((size_t)b * OUT_C + ob) * NTOK + n;
    yp[0]    = acc0;
    yp[NTOK] = acc1;
}

extern "C" void kernel_launch(void* const* d_in, const int* in_sizes, int n_in,
                              void* d_out, int out_size) {
    const float* x = (const float*)d_in[0];   // (4, 8, 65536)
    const float* w = (const float*)d_in[1];   // (4, 640, 65536)
    float* out = (float*)d_out;               // (4, 8, 65536)

    const int total = 4 * NTOK;               // 262144 tokens
    dim3 grid(total / 128, OUT_C / OH);       // (2048, 4)
    sepkan_kernel<<<grid, 128>>>(x, w, out);
}

// round 8
// speedup vs baseline: 1.2283x; 1.0060x over previous
#include <cuda_runtime.h>

// SepKANLayer1D: per-token KAN edge-spline layer.
// x: (4, 8, 65536) f32, w: (4, 640, 65536) f32, out: (4, 8, 65536) f32.
// Pure HBM stream. 4 threads/token (OH=2). Per i-iteration:
//   (1) batch-issue all 20 streaming loads,
//   (2) closed-form uniform-knot cubic basis + silu (load-independent shim),
//   (3) consume. Keeps ~20 loads/warp in flight through the compute window.

#define IN_C   8
#define OUT_C  8
#define NB     8
#define OH     2                // outputs per thread
#define NTOK   65536
#define WSIZE  640

__global__ __launch_bounds__(128, 12)   // ~42 regs: room for 20-deep load batch
void sepkan_kernel(const float* __restrict__ x,
                   const float* __restrict__ w,
                   float* __restrict__ out) {
    const int t = blockIdx.x * blockDim.x + threadIdx.x;   // 0 .. 262143 (token id)
    const int ob = blockIdx.y * OH;                        // 0,2,4,6
    const int b = t >> 16;
    const int n = t & (NTOK - 1);

    const float* xp = x + (size_t)b * IN_C * NTOK + n;
    const float* wp = w + (size_t)b * WSIZE * NTOK + n;

    float acc0 = 0.0f, acc1 = 0.0f;

    float xi_next = __ldg(xp);                 // prefetch channel 0

#pragma unroll 1
    for (int i = 0; i < IN_C; ++i) {
        const float xi = xi_next;

        // ---- (1) batch-issue the iteration's 20 streaming loads ----
        const float* wc = wp + (size_t)(i * OUT_C * NB + ob * NB) * NTOK;
        const float* wu = wp + (size_t)(IN_C * OUT_C * NB + i * OUT_C + ob) * NTOK;
        const float* wr = wp + (size_t)(IN_C * OUT_C * NB + IN_C * OUT_C + i * OUT_C + ob) * NTOK;

        float c[2 * NB];
#pragma unroll
        for (int k = 0; k < 2 * NB; ++k)
            c[k] = __ldcs(wc + (size_t)k * NTOK);
        const float u0 = __ldcs(wu);
        const float u1 = __ldcs(wu + NTOK);
        const float r0 = __ldcs(wr);
        const float r1 = __ldcs(wr + NTOK);

        if (i + 1 < IN_C) xi_next = __ldg(xp + (i + 1) * NTOK);

        // ---- (2) load-independent compute shim ----
        // closed-form uniform cubic B-spline, grid [0,1], 5 intervals:
        // m = clamp(floor(5x),0,4), u = 5x-m. Nonzero bases m..m+3:
        //   (1-u)^3/6, (3u^3-6u^2+4)/6, (-3u^3+3u^2+3u+1)/6, u^3/6
        int m = (int)(5.0f * xi);
        m = (m < 0) ? 0 : (m > 4 ? 4 : m);
        const float uu = 5.0f * xi - (float)m;
        const float vv = 1.0f - uu;
        const float uu2 = uu * uu, uu3 = uu2 * uu;
        const float bw0 = vv * vv * vv * (1.0f / 6.0f);
        const float bw1 = (3.0f * uu3 - 6.0f * uu2 + 4.0f) * (1.0f / 6.0f);
        const float bw2 = (-3.0f * uu3 + 3.0f * uu2 + 3.0f * uu + 1.0f) * (1.0f / 6.0f);
        const float bw3 = uu3 * (1.0f / 6.0f);

        float w8[NB];
#pragma unroll
        for (int k = 0; k < NB; ++k) {
            const int d = k - m;
            w8[k] = (d == 0) ? bw0 : (d == 1) ? bw1 : (d == 2) ? bw2 : (d == 3) ? bw3 : 0.0f;
        }

        const float sx = xi / (1.0f + __expf(-xi));   // silu

        // ---- (3) consume ----
        float sp0 = 0.0f, sp1 = 0.0f;
#pragma unroll
        for (int k = 0; k < NB; ++k) {
            sp0 = fmaf(w8[k], c[k],      sp0);
            sp1 = fmaf(w8[k], c[NB + k], sp1);
        }
        acc0 = fmaf(u0, sp0, acc0);
        acc1 = fmaf(u1, sp1, acc1);
        acc0 = fmaf(sx, r0, acc0);
        acc1 = fmaf(sx, r1, acc1);
    }

    float* yp = out + ((size_t)b * OUT_C + ob) * NTOK + n;
    yp[0]    = acc0;
    yp[NTOK] = acc1;
}

extern "C" void kernel_launch(void* const* d_in, const int* in_sizes, int n_in,
                              void* d_out, int out_size) {
    const float* x = (const float*)d_in[0];   // (4, 8, 65536)
    const float* w = (const float*)d_in[1];   // (4, 640, 65536)
    float* out = (float*)d_out;               // (4, 8, 65536)

    const int total = 4 * NTOK;               // 262144 tokens
    dim3 grid(total / 128, OUT_C / OH);       // (2048, 4)
    sepkan_kernel<<<grid, 128>>>(x, w, out);
}